// round 4
// baseline (speedup 1.0000x reference)
#include <cuda_runtime.h>
#include <math.h>

// ---------------------------------------------------------------------------
// SineLSTM persistent kernel v2 — 2-layer LSTM, H=512, B=128, T=512, F=64.
// 8 warps/CTA, h transposed [b][k] (pad 68), mov-free f32x2 k-pair packing.
// ---------------------------------------------------------------------------

#define NCTA 128
#define NTHR 256
#define HID  512
#define BAT  128
#define HSTR 68                    // padded staging row stride in floats
#define CHUNK_F (128 * HSTR)       // floats per staging buffer (one 64-k chunk)

typedef unsigned long long ull;

// ---------------- persistent device state ----------------------------------
__device__ __align__(16) float g_h1[2][BAT * HID];   // [buf][b][k]
__device__ __align__(16) float g_h2[2][BAT * HID];
__device__ __align__(16) float g_xT[512 * BAT];      // [t][b]
__device__ __align__(16) float g_xfeed[BAT];
__device__ volatile unsigned g_arrive[NCTA];
__device__ volatile unsigned g_sense;

// ---------------- f32x2 helpers --------------------------------------------
__device__ __forceinline__ ull fma2(ull a, ull b, ull c) {
    ull d;
    asm("fma.rn.f32x2 %0, %1, %2, %3;" : "=l"(d) : "l"(a), "l"(b), "l"(c));
    return d;
}
__device__ __forceinline__ float lo2(ull a) { return __uint_as_float((unsigned)(a & 0xffffffffull)); }
__device__ __forceinline__ float hi2(ull a) { return __uint_as_float((unsigned)(a >> 32)); }
__device__ __forceinline__ float fold4(ull e, ull o) { return (lo2(e) + hi2(e)) + (lo2(o) + hi2(o)); }

// ---------------- grid barrier ---------------------------------------------
__device__ __forceinline__ void grid_barrier(unsigned barno) {
    __threadfence();
    __syncthreads();
    if (threadIdx.x == 0) g_arrive[blockIdx.x] = barno;
    if (blockIdx.x == 0) {
        unsigned v;
        do {
            v = (threadIdx.x < NCTA) ? g_arrive[threadIdx.x] : barno;
        } while (__syncthreads_and(v >= barno) == 0);
        if (threadIdx.x == 0) g_sense = barno;
        __syncthreads();
    } else {
        if (threadIdx.x == 0) { while (g_sense < barno) {} }
        __syncthreads();
    }
    __threadfence();
}

// ---------------- cp.async staging: 64-k chunk of h, [b][k] padded ---------
__device__ __forceinline__ void stage_chunk(float* dst, const float* __restrict__ src, int tid) {
    int r = tid & 127;                 // batch row
    int p = tid >> 7;                  // half of row (32 floats each)
    unsigned d = (unsigned)__cvta_generic_to_shared(dst) + (unsigned)((r * HSTR + p * 32) * 4);
    const float* s = src + r * HID + p * 32;
#pragma unroll
    for (int j = 0; j < 8; ++j) {
        asm volatile("cp.async.cg.shared.global [%0], [%1], 16;"
                     :: "r"(d + (unsigned)j * 16u), "l"(s + j * 4) : "memory");
    }
    asm volatile("cp.async.commit_group;" ::: "memory");
}

// ---------------- one GEMM pass --------------------------------------------
// acc{E,O}[j][g] accumulate (even-k, odd-k) partial sums for unit up*2+j, gate g,
// batch b (this thread's single batch element).
__device__ __forceinline__ void gemm_pass(ull (&accE)[2][4], ull (&accO)[2][4],
                                          const float* __restrict__ wsm,
                                          const float* __restrict__ hsrc,
                                          float* hs, int up, int b, int tid) {
    stage_chunk(hs, hsrc, tid);
#pragma unroll 1
    for (int c = 0; c < 8; ++c) {
        __syncthreads();                           // buffer (c+1)&1 free
        if (c < 7) {
            stage_chunk(hs + ((c + 1) & 1) * CHUNK_F, hsrc + (c + 1) * 64, tid);
            asm volatile("cp.async.wait_group 1;" ::: "memory");
        } else {
            asm volatile("cp.async.wait_group 0;" ::: "memory");
        }
        __syncthreads();                           // chunk c staged by all threads
        const float* hrow  = hs + (c & 1) * CHUNK_F + b * HSTR;
        const float* wbase = wsm + (up * 2) * 2048 + c * 64;
#pragma unroll
        for (int kk = 0; kk < 64; kk += 4) {
            ulonglong2 hv = *(const ulonglong2*)(hrow + kk);   // (hk,hk+1),(hk+2,hk+3)
#pragma unroll
            for (int j = 0; j < 2; ++j) {
#pragma unroll
                for (int g = 0; g < 4; ++g) {
                    ulonglong2 wv = *(const ulonglong2*)(wbase + j * 2048 + g * 512 + kk);
                    accE[j][g] = fma2(hv.x, wv.x, accE[j][g]);
                    accO[j][g] = fma2(hv.y, wv.y, accO[j][g]);
                }
            }
        }
    }
}

__device__ __forceinline__ void zero_acc(ull (&accE)[2][4], ull (&accO)[2][4]) {
#pragma unroll
    for (int j = 0; j < 2; ++j)
#pragma unroll
        for (int g = 0; g < 4; ++g) { accE[j][g] = 0ull; accO[j][g] = 0ull; }
}

// ---------------- reset / transpose kernel ---------------------------------
__global__ void reset_kernel(const float* __restrict__ x, int T) {
    int idx = blockIdx.x * blockDim.x + threadIdx.x;
    if (idx < HID * BAT) {
        g_h1[0][idx] = 0.f; g_h1[1][idx] = 0.f;
        g_h2[0][idx] = 0.f; g_h2[1][idx] = 0.f;
    }
    int n = BAT * T;
    if (idx < n) {                 // x[b][t] -> xT[t][b]
        int b = idx / T, t = idx - b * T;
        g_xT[t * BAT + b] = x[idx];
    }
    if (idx < NCTA) g_arrive[idx] = 0;
    if (idx < BAT)  g_xfeed[idx] = 0.f;
    if (idx == 0)   g_sense = 0;
}

// ---------------- main persistent kernel -----------------------------------
__global__ void __launch_bounds__(NTHR, 1)
lstm_main(const float* __restrict__ Wih1, const float* __restrict__ Whh1,
          const float* __restrict__ bih1, const float* __restrict__ bhh1,
          const float* __restrict__ Wih2, const float* __restrict__ Whh2,
          const float* __restrict__ bih2, const float* __restrict__ bhh2,
          const float* __restrict__ Wout, const float* __restrict__ bout,
          float* __restrict__ out, int T, int F) {
    extern __shared__ float sm[];
    float* w1  = sm;             // [4 u][4 g][512 k]
    float* wi2 = sm + 8192;
    float* wh2 = sm + 16384;
    float* hs  = sm + 24576;     // 2 x CHUNK_F staging
    __shared__ float s_b1[16], s_b2[16], s_wx[16], s_red[8];

    const int tid  = threadIdx.x;
    const int lane = tid & 31;
    const int w    = tid >> 5;        // warp 0..7
    const int up   = w & 1;           // unit pair
    const int bq   = w >> 1;          // batch quarter
    const int b    = bq * 32 + lane;  // this thread's batch element
    const int bid  = blockIdx.x;

    // one-time weight load: [u][g][k] <- W[(g*512 + bid*4+u)*512 + k]
    for (int idx = tid; idx < 8192; idx += NTHR) {
        int u = idx >> 11, g = (idx >> 9) & 3, k = idx & 511;
        int row = g * HID + bid * 4 + u;
        w1[idx]  = Whh1[row * HID + k];
        wi2[idx] = Wih2[row * HID + k];
        wh2[idx] = Whh2[row * HID + k];
    }
    if (tid < 16) {
        int u = tid >> 2, g = tid & 3;
        int row = g * HID + bid * 4 + u;
        s_b1[tid] = bih1[row] + bhh1[row];
        s_b2[tid] = bih2[row] + bhh2[row];
        s_wx[tid] = Wih1[row];                 // W_ih1 is [4H,1]
    }
    __syncthreads();

    const float bo_out = __ldg(bout);
    const int TF = T + F;

    float c1[2] = {0.f, 0.f}, c2[2] = {0.f, 0.f};
    int p = 0, q = 0;
    unsigned barno = 0;

    ull accE[2][4], accO[2][4];

    for (int t = 0; t < TF; ++t) {
        // ---- Phase A: layer 1 -------------------------------------------
        float xv = (t < T) ? __ldcg(g_xT + t * BAT + b) : __ldcg(g_xfeed + b);
        zero_acc(accE, accO);
        gemm_pass(accE, accO, w1, g_h1[p], hs, up, b, tid);
        {
            float h1v[2];
#pragma unroll
            for (int j = 0; j < 2; ++j) {
                int ul = up * 2 + j;
                float gi = fold4(accE[j][0], accO[j][0]) + s_b1[ul * 4 + 0] + s_wx[ul * 4 + 0] * xv;
                float gf = fold4(accE[j][1], accO[j][1]) + s_b1[ul * 4 + 1] + s_wx[ul * 4 + 1] * xv;
                float gg = fold4(accE[j][2], accO[j][2]) + s_b1[ul * 4 + 2] + s_wx[ul * 4 + 2] * xv;
                float go = fold4(accE[j][3], accO[j][3]) + s_b1[ul * 4 + 3] + s_wx[ul * 4 + 3] * xv;
                float ii = 1.f / (1.f + expf(-gi));
                float ff = 1.f / (1.f + expf(-gf));
                float g_ = tanhf(gg);
                float oo = 1.f / (1.f + expf(-go));
                c1[j] = ff * c1[j] + ii * g_;
                h1v[j] = oo * tanhf(c1[j]);
            }
            __stcg((float2*)(g_h1[p ^ 1] + b * HID + bid * 4 + up * 2),
                   make_float2(h1v[0], h1v[1]));
        }
        grid_barrier(++barno);

        // ---- Phase B: layer 2 (two accumulating passes) ------------------
        zero_acc(accE, accO);
        gemm_pass(accE, accO, wi2, g_h1[p ^ 1], hs, up, b, tid);
        gemm_pass(accE, accO, wh2, g_h2[q],     hs, up, b, tid);
        {
            float h2v[2];
#pragma unroll
            for (int j = 0; j < 2; ++j) {
                int ul = up * 2 + j;
                float gi = fold4(accE[j][0], accO[j][0]) + s_b2[ul * 4 + 0];
                float gf = fold4(accE[j][1], accO[j][1]) + s_b2[ul * 4 + 1];
                float gg = fold4(accE[j][2], accO[j][2]) + s_b2[ul * 4 + 2];
                float go = fold4(accE[j][3], accO[j][3]) + s_b2[ul * 4 + 3];
                float ii = 1.f / (1.f + expf(-gi));
                float ff = 1.f / (1.f + expf(-gf));
                float g_ = tanhf(gg);
                float oo = 1.f / (1.f + expf(-go));
                c2[j] = ff * c2[j] + ii * g_;
                h2v[j] = oo * tanhf(c2[j]);
            }
            __stcg((float2*)(g_h2[q ^ 1] + b * HID + bid * 4 + up * 2),
                   make_float2(h2v[0], h2v[1]));
        }
        grid_barrier(++barno);

        // ---- Phase C: output projection (CTA bid == batch element bid) ---
        {
            const float* h2n = g_h2[q ^ 1] + bid * HID;
            float part = __ldcg(h2n + tid)       * __ldg(Wout + tid)
                       + __ldcg(h2n + tid + 256) * __ldg(Wout + tid + 256);
#pragma unroll
            for (int s = 16; s; s >>= 1) part += __shfl_xor_sync(0xffffffffu, part, s);
            if (lane == 0) s_red[w] = part;
            __syncthreads();
            if (tid == 0) {
                float o = s_red[0] + s_red[1] + s_red[2] + s_red[3]
                        + s_red[4] + s_red[5] + s_red[6] + s_red[7] + bo_out;
                out[bid * TF + t] = o;
                __stcg(g_xfeed + bid, o);
            }
        }
        if (t >= T - 1) grid_barrier(++barno);   // feedback path consumes 'out'
        else            __syncthreads();         // s_red reuse
        p ^= 1; q ^= 1;
    }
}

// ---------------------------------------------------------------------------
extern "C" void kernel_launch(void* const* d_in, const int* in_sizes, int n_in,
                              void* d_out, int out_size) {
    const float* x    = (const float*)d_in[0];
    const float* Wih1 = (const float*)d_in[2];
    const float* Whh1 = (const float*)d_in[3];
    const float* bih1 = (const float*)d_in[4];
    const float* bhh1 = (const float*)d_in[5];
    const float* Wih2 = (const float*)d_in[6];
    const float* Whh2 = (const float*)d_in[7];
    const float* bih2 = (const float*)d_in[8];
    const float* bhh2 = (const float*)d_in[9];
    const float* Wout = (const float*)d_in[10];
    const float* bout = (const float*)d_in[11];

    int T  = in_sizes[0] / BAT;       // 512
    int TF = out_size / BAT;          // 576
    int F  = TF - T;                  // 64

    const int smem = (24576 + 2 * CHUNK_F) * 4;   // 167936 B

    cudaFuncSetAttribute(lstm_main, cudaFuncAttributeMaxDynamicSharedMemorySize, smem);

    reset_kernel<<<256, 256>>>(x, T);
    lstm_main<<<NCTA, NTHR, smem>>>(Wih1, Whh1, bih1, bhh1,
                                    Wih2, Whh2, bih2, bhh2,
                                    Wout, bout, (float*)d_out, T, F);
}

// round 6
// speedup vs baseline: 1.8499x; 1.8499x over previous
#include <cuda_runtime.h>
#include <math.h>

// ---------------------------------------------------------------------------
// SineLSTM v4 — persistent mma.sync tf32 (3xTF32 split) kernel.
// 2-layer LSTM, H=512, B=128, T=512, F=64. 128 CTAs x 128 thr.
// Weights hi/lo tf32 in SMEM; h fp32 in gmem (chunked, swizzled layout),
// cp.async double-buffered; A-operand hi/lo split in registers.
// ---------------------------------------------------------------------------

#define NCTA 128
#define NTHR 128
#define HID  512
#define BAT  128

typedef unsigned int u32;

// h buffers: 64 chunks x [128 b][8 k-slots] floats (chunk = one k8 group).
// Within a chunk row b: slot pair jp holds (k8= jp, jp+4), jp XOR'ed with (b>>2)&1.
__device__ __align__(16) float g_h1[2][BAT * HID];
__device__ __align__(16) float g_h2[2][BAT * HID];
__device__ float g_xT[512 * BAT];       // [t][b]
__device__ float g_xfeed[BAT];
__device__ volatile unsigned g_arrive[NCTA];
__device__ volatile unsigned g_sense;

// ---------------- helpers ---------------------------------------------------
__device__ __forceinline__ u32 tf32hi(float x) {
    u32 r; asm("cvt.rna.tf32.f32 %0, %1;" : "=r"(r) : "f"(x)); return r;
}

__device__ __forceinline__ void mma8(float& c0, float& c1, float& c2, float& c3,
                                     u32 a0, u32 a1, u32 a2, u32 a3,
                                     u32 b0, u32 b1) {
    asm("mma.sync.aligned.m16n8k8.row.col.f32.tf32.tf32.f32 "
        "{%0,%1,%2,%3}, {%4,%5,%6,%7}, {%8,%9}, {%0,%1,%2,%3};"
        : "+f"(c0), "+f"(c1), "+f"(c2), "+f"(c3)
        : "r"(a0), "r"(a1), "r"(a2), "r"(a3), "r"(b0), "r"(b1));
}

// ---------------- grid barrier ---------------------------------------------
__device__ __forceinline__ void grid_barrier(unsigned barno) {
    __threadfence();
    __syncthreads();
    if (threadIdx.x == 0) g_arrive[blockIdx.x] = barno;
    if (blockIdx.x == 0) {
        unsigned v;
        do { v = g_arrive[threadIdx.x]; } while (__syncthreads_and(v >= barno) == 0);
        if (threadIdx.x == 0) g_sense = barno;
        __syncthreads();
    } else {
        if (threadIdx.x == 0) { while (g_sense < barno) {} }
        __syncthreads();
    }
    __threadfence();
}

// ---------------- cp.async: stage one 16KB slot (4 chunks) ------------------
__device__ __forceinline__ void stage16(float* dst, const float* __restrict__ src, int tid) {
    unsigned d = (unsigned)__cvta_generic_to_shared(dst) + (unsigned)tid * 16u;
    const float4* s = (const float4*)src + tid;
#pragma unroll
    for (int i = 0; i < 8; ++i) {
        asm volatile("cp.async.cg.shared.global [%0], [%1], 16;"
                     :: "r"(d + (unsigned)i * 2048u), "l"(s + i * 128) : "memory");
    }
    asm volatile("cp.async.commit_group;" ::: "memory");
}

// ---------------- one GEMM pass: accs += h[128,512] x W[16,512]^T -----------
__device__ __forceinline__ void mma_pass(float (&hh)[16], float (&lh)[16], float (&hl)[16],
                                         const float* __restrict__ wmat,
                                         const float* __restrict__ gsrc,
                                         float* slot0, float* slot1,
                                         int offA, int offB, int tid) {
    stage16(slot0, gsrc, tid);
    stage16(slot1, gsrc + 4096, tid);
#pragma unroll 1
    for (int it = 0; it < 16; ++it) {
        if (it < 15) asm volatile("cp.async.wait_group 1;" ::: "memory");
        else         asm volatile("cp.async.wait_group 0;" ::: "memory");
        __syncthreads();
        const float* slot = (it & 1) ? slot1 : slot0;
        const float* wit  = wmat + it * 1024;          // 4 chunks * 256 floats
#pragma unroll
        for (int c = 0; c < 4; ++c) {
            const float* hC = slot + c * 1024;
            const float* wC = wit + c * 256;
            u32 Ah[2][4], Al[2][4];
#pragma unroll
            for (int mt = 0; mt < 2; ++mt) {
                float2 P0 = *(const float2*)(hC + offA + mt * 128);        // rows r   : (a0,a2)
                float2 P1 = *(const float2*)(hC + offA + mt * 128 + 64);   // rows r+8 : (a1,a3)
                Ah[mt][0] = tf32hi(P0.x); Al[mt][0] = __float_as_uint(P0.x - __uint_as_float(Ah[mt][0]));
                Ah[mt][1] = tf32hi(P1.x); Al[mt][1] = __float_as_uint(P1.x - __uint_as_float(Ah[mt][1]));
                Ah[mt][2] = tf32hi(P0.y); Al[mt][2] = __float_as_uint(P0.y - __uint_as_float(Ah[mt][2]));
                Ah[mt][3] = tf32hi(P1.y); Al[mt][3] = __float_as_uint(P1.y - __uint_as_float(Ah[mt][3]));
            }
            uint2 Bh[2], Bl[2];
#pragma unroll
            for (int nt = 0; nt < 2; ++nt) {
                Bh[nt] = *(const uint2*)(wC + offB + nt * 64);
                Bl[nt] = *(const uint2*)(wC + 128 + offB + nt * 64);
            }
#pragma unroll
            for (int mt = 0; mt < 2; ++mt) {
#pragma unroll
                for (int nt = 0; nt < 2; ++nt) {
                    const int t4 = (mt * 2 + nt) * 4;
                    mma8(hh[t4], hh[t4+1], hh[t4+2], hh[t4+3],
                         Ah[mt][0], Ah[mt][1], Ah[mt][2], Ah[mt][3], Bh[nt].x, Bh[nt].y);
                    mma8(lh[t4], lh[t4+1], lh[t4+2], lh[t4+3],
                         Al[mt][0], Al[mt][1], Al[mt][2], Al[mt][3], Bh[nt].x, Bh[nt].y);
                    mma8(hl[t4], hl[t4+1], hl[t4+2], hl[t4+3],
                         Ah[mt][0], Ah[mt][1], Ah[mt][2], Ah[mt][3], Bl[nt].x, Bl[nt].y);
                }
            }
        }
        __syncthreads();
        if (it < 14) stage16((it & 1) ? slot1 : slot0, gsrc + (it + 2) * 4096, tid);
    }
}

__device__ __forceinline__ void zero_accs(float (&hh)[16], float (&lh)[16], float (&hl)[16]) {
#pragma unroll
    for (int i = 0; i < 16; ++i) { hh[i] = 0.f; lh[i] = 0.f; hl[i] = 0.f; }
}

// ---------------- reset / transpose ----------------------------------------
__global__ void reset_kernel(const float* __restrict__ x, int T) {
    int idx = blockIdx.x * blockDim.x + threadIdx.x;
    if (idx < BAT * HID) {
        g_h1[0][idx] = 0.f; g_h1[1][idx] = 0.f;
        g_h2[0][idx] = 0.f; g_h2[1][idx] = 0.f;
    }
    if (idx < BAT * T) {                 // x[b][t] -> xT[t][b]
        int b = idx / T, t = idx - b * T;
        g_xT[t * BAT + b] = x[idx];
    }
    if (idx < NCTA) g_arrive[idx] = 0;
    if (idx < BAT)  g_xfeed[idx] = 0.f;
    if (idx == 0)   g_sense = 0;
}

// ---------------- main persistent kernel -----------------------------------
__global__ void __launch_bounds__(NTHR, 1)
lstm_main(const float* __restrict__ Wih1, const float* __restrict__ Whh1,
          const float* __restrict__ bih1, const float* __restrict__ bhh1,
          const float* __restrict__ Wih2, const float* __restrict__ Whh2,
          const float* __restrict__ bih2, const float* __restrict__ bhh2,
          const float* __restrict__ Wout, const float* __restrict__ bout,
          float* __restrict__ out, int T, int F) {
    extern __shared__ float sm[];
    // smem: [m0=Whh1 | m1=Whh2 | m2=Wih2] each 16384 f (64 chunks * [hi128|lo128]),
    //       then 2 staging slots of 4096 f.
    float* wA  = sm;                 // Whh1
    float* wB1 = sm + 16384;         // Whh2
    float* wB2 = sm + 32768;         // Wih2
    float* slot0 = sm + 49152;
    float* slot1 = sm + 53248;
    __shared__ float s_red[4];

    const int tid  = threadIdx.x;
    const int lane = tid & 31;
    const int wid  = tid >> 5;
    const int bid  = blockIdx.x;
    const int kp   = lane & 3;            // this thread's unit (after col perm)
    const int r    = lane >> 2;           // 0..7
    const int swz  = (lane >> 4) & 1;
    const int jp2  = 2 * (kp ^ swz);
    const int offA = (wid * 32 + r) * 8 + jp2;
    const int offB = r * 8 + jp2;

    // ---- one-time: split weights into SMEM hi/lo chunked layout -----------
    {
        const float* Ws[3] = { Whh1, Whh2, Wih2 };
        float* Wd[3] = { wA, wB1, wB2 };
        for (int idx = tid; idx < 8192; idx += NTHR) {
            int n = idx >> 9, k = idx & 511;
            int u = (n & 7) >> 1, g = (n & 1) + 2 * (n >> 3);
            int row = g * HID + bid * 4 + u;
            int pos = (k >> 3) * 256 + n * 8 + 2 * ((k & 3) ^ ((n >> 2) & 1)) + ((k >> 2) & 1);
#pragma unroll
            for (int m = 0; m < 3; ++m) {
                float w = __ldg(Ws[m] + row * HID + k);
                u32 hi = tf32hi(w);
                Wd[m][pos]       = __uint_as_float(hi);
                Wd[m][pos + 128] = w - __uint_as_float(hi);
            }
        }
    }
    // per-thread bias/wx for unit kp
    float b1g[4], b2g[4], wxg[4];
#pragma unroll
    for (int g = 0; g < 4; ++g) {
        int row = g * HID + bid * 4 + kp;
        b1g[g] = __ldg(bih1 + row) + __ldg(bhh1 + row);
        b2g[g] = __ldg(bih2 + row) + __ldg(bhh2 + row);
        wxg[g] = __ldg(Wih1 + row);
    }
    const float bo_out = __ldg(bout);
    __syncthreads();

    // this thread's 4 cells: cc = mt*2+rh -> batch b
    int bArr[4];
#pragma unroll
    for (int cc = 0; cc < 4; ++cc)
        bArr[cc] = wid * 32 + (cc >> 1) * 16 + (cc & 1) * 8 + r;
    // h store base: k = 4*bid + kp
    const int hstore = (bid >> 1) * 1024 + (bid & 1) + jp2 + (wid * 32 + r) * 8;

    const int TF = T + F;
    float c1[4] = {0, 0, 0, 0}, c2[4] = {0, 0, 0, 0};
    int p = 0, q = 0;
    unsigned barno = 0;
    float hh[16], lh[16], hl[16];

    for (int t = 0; t < TF; ++t) {
        // ---- Phase A: layer 1 gates = h1_old x Whh1^T ---------------------
        const float* xsrc = (t < T) ? (g_xT + t * BAT) : g_xfeed;
        float xv[4];
#pragma unroll
        for (int cc = 0; cc < 4; ++cc) xv[cc] = __ldcg(xsrc + bArr[cc]);

        zero_accs(hh, lh, hl);
        mma_pass(hh, lh, hl, wA, g_h1[p], slot0, slot1, offA, offB, tid);
#pragma unroll
        for (int cc = 0; cc < 4; ++cc) {
            int mt = cc >> 1, rh = cc & 1;
            int e0 = (mt * 2 + 0) * 4 + rh * 2;
            int e1 = (mt * 2 + 1) * 4 + rh * 2;
            float gi = hh[e0]   + lh[e0]   + hl[e0]   + b1g[0] + wxg[0] * xv[cc];
            float gf = hh[e0+1] + lh[e0+1] + hl[e0+1] + b1g[1] + wxg[1] * xv[cc];
            float gg = hh[e1]   + lh[e1]   + hl[e1]   + b1g[2] + wxg[2] * xv[cc];
            float go = hh[e1+1] + lh[e1+1] + hl[e1+1] + b1g[3] + wxg[3] * xv[cc];
            float ii = 1.f / (1.f + expf(-gi));
            float ff = 1.f / (1.f + expf(-gf));
            float g_ = tanhf(gg);
            float oo = 1.f / (1.f + expf(-go));
            c1[cc] = ff * c1[cc] + ii * g_;
            float h1v = oo * tanhf(c1[cc]);
            __stcg(g_h1[p ^ 1] + hstore + mt * 128 + rh * 64, h1v);
        }

        // ---- Phase B1: h2_old x Whh2^T (no barrier needed yet) ------------
        zero_accs(hh, lh, hl);
        mma_pass(hh, lh, hl, wB1, g_h2[q], slot0, slot1, offA, offB, tid);

        grid_barrier(++barno);            // h1_new now visible everywhere

        // ---- Phase B2: += h1_new x Wih2^T ---------------------------------
        mma_pass(hh, lh, hl, wB2, g_h1[p ^ 1], slot0, slot1, offA, offB, tid);
#pragma unroll
        for (int cc = 0; cc < 4; ++cc) {
            int mt = cc >> 1, rh = cc & 1;
            int e0 = (mt * 2 + 0) * 4 + rh * 2;
            int e1 = (mt * 2 + 1) * 4 + rh * 2;
            float gi = hh[e0]   + lh[e0]   + hl[e0]   + b2g[0];
            float gf = hh[e0+1] + lh[e0+1] + hl[e0+1] + b2g[1];
            float gg = hh[e1]   + lh[e1]   + hl[e1]   + b2g[2];
            float go = hh[e1+1] + lh[e1+1] + hl[e1+1] + b2g[3];
            float ii = 1.f / (1.f + expf(-gi));
            float ff = 1.f / (1.f + expf(-gf));
            float g_ = tanhf(gg);
            float oo = 1.f / (1.f + expf(-go));
            c2[cc] = ff * c2[cc] + ii * g_;
            float h2v = oo * tanhf(c2[cc]);
            __stcg(g_h2[q ^ 1] + hstore + mt * 128 + rh * 64, h2v);
        }
        grid_barrier(++barno);            // h2_new visible

        // ---- Phase C: projection (CTA bid == batch element bid) -----------
        {
            const float* h2n = g_h2[q ^ 1];
            int hb = (tid >> 1) * 1024 + bid * 8 + (tid & 1);
            int swzb = (bid >> 2) & 1;
            float4 w4 = __ldg((const float4*)(Wout + tid * 4));
            float wv[4] = { w4.x, w4.y, w4.z, w4.w };
            float part = 0.f;
#pragma unroll
            for (int kq = 0; kq < 4; ++kq)
                part += __ldcg(h2n + hb + 2 * (kq ^ swzb)) * wv[kq];
#pragma unroll
            for (int s = 16; s; s >>= 1) part += __shfl_xor_sync(0xffffffffu, part, s);
            if (lane == 0) s_red[wid] = part;
            __syncthreads();
            if (tid == 0) {
                float o = s_red[0] + s_red[1] + s_red[2] + s_red[3] + bo_out;
                out[bid * TF + t] = o;
                __stcg(g_xfeed + bid, o);
            }
        }
        if (t >= T - 1) grid_barrier(++barno);   // feedback consumes 'out'
        else            __syncthreads();         // s_red reuse
        p ^= 1; q ^= 1;
    }
}

// ---------------------------------------------------------------------------
extern "C" void kernel_launch(void* const* d_in, const int* in_sizes, int n_in,
                              void* d_out, int out_size) {
    const float* x    = (const float*)d_in[0];
    const float* Wih1 = (const float*)d_in[2];
    const float* Whh1 = (const float*)d_in[3];
    const float* bih1 = (const float*)d_in[4];
    const float* bhh1 = (const float*)d_in[5];
    const float* Wih2 = (const float*)d_in[6];
    const float* Whh2 = (const float*)d_in[7];
    const float* bih2 = (const float*)d_in[8];
    const float* bhh2 = (const float*)d_in[9];
    const float* Wout = (const float*)d_in[10];
    const float* bout = (const float*)d_in[11];

    int T  = in_sizes[0] / BAT;       // 512
    int TF = out_size / BAT;          // 576
    int F  = TF - T;                  // 64

    const int smem = 57344 * 4;       // 229376 B dynamic

    cudaFuncSetAttribute(lstm_main, cudaFuncAttributeMaxDynamicSharedMemorySize, smem);

    reset_kernel<<<256, 256>>>(x, T);
    lstm_main<<<NCTA, NTHR, smem>>>(Wih1, Whh1, bih1, bhh1,
                                    Wih2, Whh2, bih2, bhh2,
                                    Wout, bout, (float*)d_out, T, F);
}

// round 7
// speedup vs baseline: 2.6025x; 1.4068x over previous
#include <cuda_runtime.h>
#include <math.h>

// ---------------------------------------------------------------------------
// SineLSTM v5 — persistent mma.sync tf32 (3xTF32) kernel, sync-free GEMM.
// 2-layer LSTM, H=512, B=128, T=512, F=64. 128 CTAs x 256 thr (8 warps).
// h lives in gmem in mma-fragment order ([mtile][k8][lane][a0..a3]); read with
// __ldcg float4 (L2-coherent). Weights hi/lo tf32 in SMEM. No smem staging,
// no __syncthreads inside GEMM passes.
// ---------------------------------------------------------------------------

#define NCTA 128
#define NTHR 256
#define HID  512
#define BAT  128

typedef unsigned int u32;

// h buffers in fragment order: float index = ((mtile*64 + k8)*32 + lane)*4 + a
__device__ __align__(16) float g_h1[2][BAT * HID];
__device__ __align__(16) float g_h2[2][BAT * HID];
__device__ float g_xT[512 * BAT];       // [t][b]
__device__ float g_xfeed[BAT];
__device__ volatile unsigned g_arrive[NCTA];
__device__ volatile unsigned g_sense;

// ---------------- helpers ---------------------------------------------------
__device__ __forceinline__ u32 tf32hi(float x) {
    u32 r; asm("cvt.rna.tf32.f32 %0, %1;" : "=r"(r) : "f"(x)); return r;
}

__device__ __forceinline__ void mma8(float* c,
                                     u32 a0, u32 a1, u32 a2, u32 a3,
                                     u32 b0, u32 b1) {
    asm("mma.sync.aligned.m16n8k8.row.col.f32.tf32.tf32.f32 "
        "{%0,%1,%2,%3}, {%4,%5,%6,%7}, {%8,%9}, {%0,%1,%2,%3};"
        : "+f"(c[0]), "+f"(c[1]), "+f"(c[2]), "+f"(c[3])
        : "r"(a0), "r"(a1), "r"(a2), "r"(a3), "r"(b0), "r"(b1));
}

// ---------------- grid barrier ---------------------------------------------
__device__ __forceinline__ void grid_barrier(unsigned barno) {
    __threadfence();
    __syncthreads();
    if (threadIdx.x == 0) g_arrive[blockIdx.x] = barno;
    if (blockIdx.x == 0) {
        unsigned v;
        do {
            v = (threadIdx.x < NCTA) ? g_arrive[threadIdx.x] : barno;
        } while (__syncthreads_and(v >= barno) == 0);
        if (threadIdx.x == 0) g_sense = barno;
        __syncthreads();
    } else {
        if (threadIdx.x == 0) { while (g_sense < barno) {} }
        __syncthreads();
    }
    __threadfence();
}

// ---------------- one GEMM pass: acc += h[128,512] x W[16,512]^T ------------
// acc[term][nt][4]; term 0 = hh, 1 = lh, 2 = hl. Warp wid owns m-tile wid.
__device__ __forceinline__ void mma_pass(float (&acc)[3][2][4],
                                         const float* __restrict__ wsm,
                                         const float* __restrict__ ga,
                                         int lane, int wid) {
    const float4* ap = (const float4*)ga + wid * 2048 + lane;   // stride 32 per k8
    float4 ab[4];
#pragma unroll
    for (int i = 0; i < 4; ++i) ab[i] = __ldcg(ap + i * 32);

#pragma unroll 4
    for (int k8 = 0; k8 < 64; ++k8) {
        float4 a = ab[k8 & 3];
        if (k8 < 60) ab[k8 & 3] = __ldcg(ap + (k8 + 4) * 32);

        const float* wb = wsm + k8 * 256 + (lane << 2);
        float4 bh = *(const float4*)(wb);          // (nt0.b0, nt0.b1, nt1.b0, nt1.b1) hi
        float4 bl = *(const float4*)(wb + 128);    // same, lo

        u32 ah0 = tf32hi(a.x), ah1 = tf32hi(a.y), ah2 = tf32hi(a.z), ah3 = tf32hi(a.w);
        u32 al0 = __float_as_uint(a.x - __uint_as_float(ah0));
        u32 al1 = __float_as_uint(a.y - __uint_as_float(ah1));
        u32 al2 = __float_as_uint(a.z - __uint_as_float(ah2));
        u32 al3 = __float_as_uint(a.w - __uint_as_float(ah3));

        u32 bh0 = __float_as_uint(bh.x), bh1 = __float_as_uint(bh.y);
        u32 bh2 = __float_as_uint(bh.z), bh3 = __float_as_uint(bh.w);
        u32 bl0 = __float_as_uint(bl.x), bl1 = __float_as_uint(bl.y);
        u32 bl2 = __float_as_uint(bl.z), bl3 = __float_as_uint(bl.w);

        mma8(acc[0][0], ah0, ah1, ah2, ah3, bh0, bh1);   // hh nt0
        mma8(acc[1][0], al0, al1, al2, al3, bh0, bh1);   // lh nt0
        mma8(acc[2][0], ah0, ah1, ah2, ah3, bl0, bl1);   // hl nt0
        mma8(acc[0][1], ah0, ah1, ah2, ah3, bh2, bh3);   // hh nt1
        mma8(acc[1][1], al0, al1, al2, al3, bh2, bh3);   // lh nt1
        mma8(acc[2][1], ah0, ah1, ah2, ah3, bl2, bl3);   // hl nt1
    }
}

__device__ __forceinline__ void zero_acc(float (&acc)[3][2][4]) {
#pragma unroll
    for (int t = 0; t < 3; ++t)
#pragma unroll
        for (int n = 0; n < 2; ++n)
#pragma unroll
            for (int i = 0; i < 4; ++i) acc[t][n][i] = 0.f;
}

// ---------------- reset / transpose ----------------------------------------
__global__ void reset_kernel(const float* __restrict__ x, int T) {
    int idx = blockIdx.x * blockDim.x + threadIdx.x;
    if (idx < BAT * HID) {
        g_h1[0][idx] = 0.f; g_h1[1][idx] = 0.f;
        g_h2[0][idx] = 0.f; g_h2[1][idx] = 0.f;
    }
    if (idx < BAT * T) {                 // x[b][t] -> xT[t][b]
        int b = idx / T, t = idx - b * T;
        g_xT[t * BAT + b] = x[idx];
    }
    if (idx < NCTA) g_arrive[idx] = 0;
    if (idx < BAT)  g_xfeed[idx] = 0.f;
    if (idx == 0)   g_sense = 0;
}

// ---------------- main persistent kernel -----------------------------------
__global__ void __launch_bounds__(NTHR, 1)
lstm_main(const float* __restrict__ Wih1, const float* __restrict__ Whh1,
          const float* __restrict__ bih1, const float* __restrict__ bhh1,
          const float* __restrict__ Wih2, const float* __restrict__ Whh2,
          const float* __restrict__ bih2, const float* __restrict__ bhh2,
          const float* __restrict__ Wout, const float* __restrict__ bout,
          float* __restrict__ out, int T, int F) {
    extern __shared__ float sm[];
    float* wA  = sm;                 // Whh1: 64 k8 x (128 hi + 128 lo)
    float* wB1 = sm + 16384;         // Whh2
    float* wB2 = sm + 32768;         // Wih2
    __shared__ float s_red[8];

    const int tid  = threadIdx.x;
    const int lane = tid & 31;
    const int wid  = tid >> 5;            // warp 0..7 = m-tile
    const int bid  = blockIdx.x;
    const int r    = lane >> 2;           // fragment row 0..7
    const int u    = lane & 3;            // this thread's hidden unit (of CTA's 4)

    // ---- one-time: split weights into SMEM fragment layout ----------------
    // B element (n,k): n -> u' = (n&7)>>1, g = (n&1)+2*(n>>3); W row = g*512+bid*4+u'
    // storage: k8*256 + [hi:0|lo:128] + ((n&7)*4 + (k&3))*4 + (n>>3)*2 + ((k>>2)&1)
    {
        const float* Ws[3] = { Whh1, Whh2, Wih2 };
        float* Wd[3] = { wA, wB1, wB2 };
        for (int idx = tid; idx < 8192; idx += NTHR) {
            int n = idx >> 9, k = idx & 511;
            int uu = (n & 7) >> 1, g = (n & 1) + 2 * (n >> 3);
            int row = g * HID + bid * 4 + uu;
            int pos = (k >> 3) * 256 + ((n & 7) * 4 + (k & 3)) * 4
                    + ((n >> 3) << 1) + ((k >> 2) & 1);
#pragma unroll
            for (int m = 0; m < 3; ++m) {
                float w = __ldg(Ws[m] + row * HID + k);
                u32 hi = tf32hi(w);
                Wd[m][pos]       = __uint_as_float(hi);
                Wd[m][pos + 128] = w - __uint_as_float(hi);
            }
        }
    }
    // per-thread bias / x-weight for unit u
    float b1g[4], b2g[4], wxg[4];
#pragma unroll
    for (int g = 0; g < 4; ++g) {
        int row = g * HID + bid * 4 + u;
        b1g[g] = __ldg(bih1 + row) + __ldg(bhh1 + row);
        b2g[g] = __ldg(bih2 + row) + __ldg(bhh2 + row);
        wxg[g] = __ldg(Wih1 + row);
    }
    const float bo_out = __ldg(bout);
    __syncthreads();

    // this thread's 2 cells: batches b0 = wid*16 + r, b1 = b0 + 8
    const int b0 = wid * 16 + r;
    const int b1 = b0 + 8;
    // h writeback: fragment addr for k = 4*bid + u, rows b0/b1 -> adjacent floats
    const int hstore = (((wid * 64 + (bid >> 1)) * 32 + (r << 2) + u) << 2)
                     + ((bid & 1) << 1);

    const int TF = T + F;
    float c1[2] = {0.f, 0.f}, c2[2] = {0.f, 0.f};
    int p = 0, q = 0;
    unsigned barno = 0;
    float acc[3][2][4];

    for (int t = 0; t < TF; ++t) {
        // ---- Phase A: layer 1 gates = h1_old x Whh1^T ---------------------
        const float* xsrc = (t < T) ? (g_xT + t * BAT) : g_xfeed;
        float xv0 = __ldcg(xsrc + b0);
        float xv1 = __ldcg(xsrc + b1);

        zero_acc(acc);
        mma_pass(acc, wA, g_h1[p], lane, wid);
        {
            float h1v[2];
            float xq[2] = { xv0, xv1 };
#pragma unroll
            for (int j = 0; j < 2; ++j) {
                float gi = acc[0][0][j*2]   + acc[1][0][j*2]   + acc[2][0][j*2]   + b1g[0] + wxg[0] * xq[j];
                float gf = acc[0][0][j*2+1] + acc[1][0][j*2+1] + acc[2][0][j*2+1] + b1g[1] + wxg[1] * xq[j];
                float gg = acc[0][1][j*2]   + acc[1][1][j*2]   + acc[2][1][j*2]   + b1g[2] + wxg[2] * xq[j];
                float go = acc[0][1][j*2+1] + acc[1][1][j*2+1] + acc[2][1][j*2+1] + b1g[3] + wxg[3] * xq[j];
                float ii = 1.f / (1.f + expf(-gi));
                float ff = 1.f / (1.f + expf(-gf));
                float g_ = tanhf(gg);
                float oo = 1.f / (1.f + expf(-go));
                c1[j] = ff * c1[j] + ii * g_;
                h1v[j] = oo * tanhf(c1[j]);
            }
            __stcg((float2*)(g_h1[p ^ 1] + hstore), make_float2(h1v[0], h1v[1]));
        }

        // ---- Phase B1: h2_old x Whh2^T (independent of h1_new) ------------
        zero_acc(acc);
        mma_pass(acc, wB1, g_h2[q], lane, wid);

        grid_barrier(++barno);            // h1_new visible chip-wide

        // ---- Phase B2: += h1_new x Wih2^T ---------------------------------
        mma_pass(acc, wB2, g_h1[p ^ 1], lane, wid);
        {
            float h2v[2];
#pragma unroll
            for (int j = 0; j < 2; ++j) {
                float gi = acc[0][0][j*2]   + acc[1][0][j*2]   + acc[2][0][j*2]   + b2g[0];
                float gf = acc[0][0][j*2+1] + acc[1][0][j*2+1] + acc[2][0][j*2+1] + b2g[1];
                float gg = acc[0][1][j*2]   + acc[1][1][j*2]   + acc[2][1][j*2]   + b2g[2];
                float go = acc[0][1][j*2+1] + acc[1][1][j*2+1] + acc[2][1][j*2+1] + b2g[3];
                float ii = 1.f / (1.f + expf(-gi));
                float ff = 1.f / (1.f + expf(-gf));
                float g_ = tanhf(gg);
                float oo = 1.f / (1.f + expf(-go));
                c2[j] = ff * c2[j] + ii * g_;
                h2v[j] = oo * tanhf(c2[j]);
            }
            __stcg((float2*)(g_h2[q ^ 1] + hstore), make_float2(h2v[0], h2v[1]));
        }
        grid_barrier(++barno);            // h2_new visible chip-wide

        // ---- Phase C: projection (CTA bid == batch element bid) -----------
        {
            const float* h2n = g_h2[q ^ 1];
            float part = 0.f;
#pragma unroll
            for (int e = 0; e < 2; ++e) {
                int k = 2 * tid + e;
                int addr = (((bid >> 4) * 64 + (k >> 3)) * 32
                            + ((bid & 7) << 2) + (k & 3)) * 4
                         + (((k >> 2) & 1) << 1) + ((bid >> 3) & 1);
                part += __ldcg(h2n + addr) * __ldg(Wout + k);
            }
#pragma unroll
            for (int s = 16; s; s >>= 1) part += __shfl_xor_sync(0xffffffffu, part, s);
            if (lane == 0) s_red[wid] = part;
            __syncthreads();
            if (tid == 0) {
                float o = s_red[0] + s_red[1] + s_red[2] + s_red[3]
                        + s_red[4] + s_red[5] + s_red[6] + s_red[7] + bo_out;
                out[bid * TF + t] = o;
                __stcg(g_xfeed + bid, o);
            }
        }
        if (t >= T - 1) grid_barrier(++barno);   // feedback consumes 'out'
        else            __syncthreads();         // s_red reuse
        p ^= 1; q ^= 1;
    }
}

// ---------------------------------------------------------------------------
extern "C" void kernel_launch(void* const* d_in, const int* in_sizes, int n_in,
                              void* d_out, int out_size) {
    const float* x    = (const float*)d_in[0];
    const float* Wih1 = (const float*)d_in[2];
    const float* Whh1 = (const float*)d_in[3];
    const float* bih1 = (const float*)d_in[4];
    const float* bhh1 = (const float*)d_in[5];
    const float* Wih2 = (const float*)d_in[6];
    const float* Whh2 = (const float*)d_in[7];
    const float* bih2 = (const float*)d_in[8];
    const float* bhh2 = (const float*)d_in[9];
    const float* Wout = (const float*)d_in[10];
    const float* bout = (const float*)d_in[11];

    int T  = in_sizes[0] / BAT;       // 512
    int TF = out_size / BAT;          // 576
    int F  = TF - T;                  // 64

    const int smem = 49152 * 4;       // 196608 B: 3 weight matrices hi/lo

    cudaFuncSetAttribute(lstm_main, cudaFuncAttributeMaxDynamicSharedMemorySize, smem);

    reset_kernel<<<256, 256>>>(x, T);
    lstm_main<<<NCTA, NTHR, smem>>>(Wih1, Whh1, bih1, bhh1,
                                    Wih2, Whh2, bih2, bhh2,
                                    Wout, bout, (float*)d_out, T, F);
}

// round 8
// speedup vs baseline: 3.6681x; 1.4095x over previous
#include <cuda_runtime.h>
#include <cuda_bf16.h>
#include <math.h>

// ---------------------------------------------------------------------------
// SineLSTM v6 — persistent mma.sync bf16 m16n8k16 (3-term split) kernel.
// 2-layer LSTM, H=512, B=128, T=512, F=64. 128 CTAs x 256 thr (8 warps).
// h pre-split into bf16 hi/lo, stored in gmem in mma-fragment order; weights
// pre-split into SMEM fragment order. Zero conversions in the hot loop.
// ---------------------------------------------------------------------------

#define NCTA 128
#define NTHR 256
#define HID  512
#define BAT  128

typedef unsigned int u32;

// fragment buffers: [mtile(8)][k16(32)][lane(32)] x uint4 (regs a0..a3, bf16x2)
__device__ __align__(16) uint4 g_h1h[2][8192];
__device__ __align__(16) uint4 g_h1l[2][8192];
__device__ __align__(16) uint4 g_h2h[2][8192];
__device__ __align__(16) uint4 g_h2l[2][8192];
__device__ __align__(16) float g_h2p[2][BAT * HID];   // plain [b][k] for projection
__device__ float g_xT[512 * BAT];                     // [t][b]
__device__ float g_xfeed[BAT];
__device__ volatile unsigned g_arrive[NCTA];
__device__ volatile unsigned g_sense;

// ---------------- helpers ---------------------------------------------------
__device__ __forceinline__ unsigned short bfbits(__nv_bfloat16 v) {
    return reinterpret_cast<unsigned short&>(v);
}
__device__ __forceinline__ void st16g(void* base, int word, int half, unsigned short v) {
    asm volatile("st.global.cg.u16 [%0], %1;"
                 :: "l"((char*)base + (size_t)word * 4 + half * 2), "h"(v) : "memory");
}

__device__ __forceinline__ void mma16(float* c, uint4 a, u32 b0, u32 b1) {
    asm("mma.sync.aligned.m16n8k16.row.col.f32.bf16.bf16.f32 "
        "{%0,%1,%2,%3}, {%4,%5,%6,%7}, {%8,%9}, {%0,%1,%2,%3};"
        : "+f"(c[0]), "+f"(c[1]), "+f"(c[2]), "+f"(c[3])
        : "r"(a.x), "r"(a.y), "r"(a.z), "r"(a.w), "r"(b0), "r"(b1));
}

// ---------------- grid barrier ---------------------------------------------
__device__ __forceinline__ void grid_barrier(unsigned barno) {
    __threadfence();
    __syncthreads();
    if (threadIdx.x == 0) g_arrive[blockIdx.x] = barno;
    if (blockIdx.x == 0) {
        unsigned v;
        do {
            v = (threadIdx.x < NCTA) ? g_arrive[threadIdx.x] : barno;
        } while (__syncthreads_and(v >= barno) == 0);
        if (threadIdx.x == 0) g_sense = barno;
        __syncthreads();
    } else {
        if (threadIdx.x == 0) { while (g_sense < barno) {} }
        __syncthreads();
    }
    __threadfence();
}

// ---------------- one GEMM pass: acc += h[128,512] x W[16,512]^T ------------
// acc[term][nt][4]; 0 = hi*hi, 1 = lo*hi, 2 = hi*lo. Warp wid owns m-tile wid.
__device__ __forceinline__ void mma_pass(float (&acc)[3][2][4],
                                         const uint4* __restrict__ whi,
                                         const uint4* __restrict__ wlo,
                                         const uint4* __restrict__ ghi,
                                         const uint4* __restrict__ glo,
                                         int lane, int wid) {
    const uint4* aph = ghi + wid * 1024 + lane;   // stride 32 uint4 per k16
    const uint4* apl = glo + wid * 1024 + lane;
    uint4 pf_h[4], pf_l[4];
#pragma unroll
    for (int i = 0; i < 4; ++i) { pf_h[i] = __ldcg(aph + i * 32); pf_l[i] = __ldcg(apl + i * 32); }

#pragma unroll 4
    for (int k16 = 0; k16 < 32; ++k16) {
        uint4 Ah = pf_h[k16 & 3], Al = pf_l[k16 & 3];
        if (k16 < 28) {
            pf_h[k16 & 3] = __ldcg(aph + (k16 + 4) * 32);
            pf_l[k16 & 3] = __ldcg(apl + (k16 + 4) * 32);
        }
        uint4 Bh = whi[k16 * 32 + lane];
        uint4 Bl = wlo[k16 * 32 + lane];
        mma16(acc[0][0], Ah, Bh.x, Bh.y);    // hh nt0
        mma16(acc[1][0], Al, Bh.x, Bh.y);    // lh nt0
        mma16(acc[2][0], Ah, Bl.x, Bl.y);    // hl nt0
        mma16(acc[0][1], Ah, Bh.z, Bh.w);    // hh nt1
        mma16(acc[1][1], Al, Bh.z, Bh.w);    // lh nt1
        mma16(acc[2][1], Ah, Bl.z, Bl.w);    // hl nt1
    }
}

__device__ __forceinline__ void zero_acc(float (&acc)[3][2][4]) {
#pragma unroll
    for (int t = 0; t < 3; ++t)
#pragma unroll
        for (int n = 0; n < 2; ++n)
#pragma unroll
            for (int i = 0; i < 4; ++i) acc[t][n][i] = 0.f;
}

// ---------------- reset / transpose ----------------------------------------
__global__ void reset_kernel(const float* __restrict__ x, int T) {
    int idx = blockIdx.x * blockDim.x + threadIdx.x;
    uint4 z4 = make_uint4(0, 0, 0, 0);
    if (idx < 16384) {       // 2 phases x 8192 uint4 per array
        ((uint4*)g_h1h)[idx] = z4; ((uint4*)g_h1l)[idx] = z4;
        ((uint4*)g_h2h)[idx] = z4; ((uint4*)g_h2l)[idx] = z4;
    }
    if (idx < 2 * BAT * HID) ((float*)g_h2p)[idx] = 0.f;
    if (idx < BAT * T) {                 // x[b][t] -> xT[t][b]
        int b = idx / T, t = idx - b * T;
        g_xT[t * BAT + b] = x[idx];
    }
    if (idx < NCTA) g_arrive[idx] = 0;
    if (idx < BAT)  g_xfeed[idx] = 0.f;
    if (idx == 0)   g_sense = 0;
}

// ---------------- main persistent kernel -----------------------------------
__global__ void __launch_bounds__(NTHR, 1)
lstm_main(const float* __restrict__ Wih1, const float* __restrict__ Whh1,
          const float* __restrict__ bih1, const float* __restrict__ bhh1,
          const float* __restrict__ Wih2, const float* __restrict__ Whh2,
          const float* __restrict__ bih2, const float* __restrict__ bhh2,
          const float* __restrict__ Wout, const float* __restrict__ bout,
          float* __restrict__ out, int T, int F) {
    extern __shared__ float sm[];
    // per matrix: hi 4096 floats (1024 uint4), lo 4096 floats. Order A,B1,B2.
    __shared__ float s_red[8];

    const int tid  = threadIdx.x;
    const int lane = tid & 31;
    const int wid  = tid >> 5;            // warp = m-tile (16 batches)
    const int bid  = blockIdx.x;
    const int r    = lane >> 2;           // fragment row 0..7
    const int u    = lane & 3;            // this thread's hidden unit (of CTA's 4)

    // ---- one-time: split weights into SMEM bf16 fragment layout -----------
    // n(g,u') = (g&1) + 2u' + 8(g>>1); inverse u'=(n&7)>>1, g=(n&1)+2*(n>>3)
    {
        const float* Ws[3] = { Whh1, Whh2, Wih2 };
        for (int idx = tid; idx < 8192; idx += NTHR) {
            int n = idx >> 9, k = idx & 511;
            int uu = (n & 7) >> 1, g = (n & 1) + 2 * (n >> 3);
            int row = g * HID + bid * 4 + uu;
            int k16 = k >> 4, kc = k & 15;
            int ln  = (n & 7) * 4 + ((kc & 7) >> 1);
            int word = (k16 * 32 + ln) * 4 + (n >> 3) * 2 + (kc >> 3);
            int half = kc & 1;
#pragma unroll
            for (int m = 0; m < 3; ++m) {
                float w = __ldg(Ws[m] + row * HID + k);
                __nv_bfloat16 bh = __float2bfloat16(w);
                __nv_bfloat16 bl = __float2bfloat16(w - __bfloat162float(bh));
                ((unsigned short*)(sm + m * 8192))[word * 2 + half]        = bfbits(bh);
                ((unsigned short*)(sm + m * 8192 + 4096))[word * 2 + half] = bfbits(bl);
            }
        }
    }
    // per-thread bias / x-weight for unit u
    float b1g[4], b2g[4], wxg[4];
#pragma unroll
    for (int g = 0; g < 4; ++g) {
        int row = g * HID + bid * 4 + u;
        b1g[g] = __ldg(bih1 + row) + __ldg(bhh1 + row);
        b2g[g] = __ldg(bih2 + row) + __ldg(bhh2 + row);
        wxg[g] = __ldg(Wih1 + row);
    }
    const float bo_out = __ldg(bout);
    __syncthreads();

    const uint4* whiA  = (const uint4*)sm;
    const uint4* wloA  = (const uint4*)(sm + 4096);
    const uint4* whiB1 = (const uint4*)(sm + 8192);
    const uint4* wloB1 = (const uint4*)(sm + 12288);
    const uint4* whiB2 = (const uint4*)(sm + 16384);
    const uint4* wloB2 = (const uint4*)(sm + 20480);

    // this thread's 2 cells: batches b0 = wid*16 + r, b1 = b0 + 8; k = 4*bid+u
    const int b0 = wid * 16 + r;
    const int b1 = b0 + 8;
    const int kk = 4 * bid + u;
    // fragment store coords for (row r / r+8, col kc) in k16 tile q16
    const int q16 = bid >> 2;
    const int kc  = 4 * (bid & 3) + u;
    const int Ls  = r * 4 + ((kc & 7) >> 1);
    const int rb  = (kc >= 8) ? 2 : 0;
    const int hf  = kc & 1;
    const int fidx = ((wid * 32 + q16) * 32 + Ls) * 4 + rb;   // u32 index; +1 for b1

    const int TF = T + F;
    float c1[2] = {0.f, 0.f}, c2[2] = {0.f, 0.f};
    int p = 0, q = 0;
    unsigned barno = 0;
    float acc[3][2][4];

    for (int t = 0; t < TF; ++t) {
        // ---- Phase A: layer 1 gates = h1_old x Whh1^T ---------------------
        const float* xsrc = (t < T) ? (g_xT + t * BAT) : g_xfeed;
        float xq[2] = { __ldcg(xsrc + b0), __ldcg(xsrc + b1) };

        zero_acc(acc);
        mma_pass(acc, whiA, wloA, g_h1h[p], g_h1l[p], lane, wid);
#pragma unroll
        for (int j = 0; j < 2; ++j) {
            float gi = acc[0][0][j*2]   + acc[1][0][j*2]   + acc[2][0][j*2]   + b1g[0] + wxg[0] * xq[j];
            float gf = acc[0][0][j*2+1] + acc[1][0][j*2+1] + acc[2][0][j*2+1] + b1g[1] + wxg[1] * xq[j];
            float gg = acc[0][1][j*2]   + acc[1][1][j*2]   + acc[2][1][j*2]   + b1g[2] + wxg[2] * xq[j];
            float go = acc[0][1][j*2+1] + acc[1][1][j*2+1] + acc[2][1][j*2+1] + b1g[3] + wxg[3] * xq[j];
            float ii = 1.f / (1.f + expf(-gi));
            float ff = 1.f / (1.f + expf(-gf));
            float g_ = tanhf(gg);
            float oo = 1.f / (1.f + expf(-go));
            c1[j] = ff * c1[j] + ii * g_;
            float hv = oo * tanhf(c1[j]);
            __nv_bfloat16 bh = __float2bfloat16(hv);
            __nv_bfloat16 bl = __float2bfloat16(hv - __bfloat162float(bh));
            st16g(g_h1h[p ^ 1], fidx + j, hf, bfbits(bh));
            st16g(g_h1l[p ^ 1], fidx + j, hf, bfbits(bl));
        }

        // ---- Phase B1: h2_old x Whh2^T (independent of h1_new) ------------
        zero_acc(acc);
        mma_pass(acc, whiB1, wloB1, g_h2h[q], g_h2l[q], lane, wid);

        grid_barrier(++barno);            // h1_new visible chip-wide

        // ---- Phase B2: += h1_new x Wih2^T ---------------------------------
        mma_pass(acc, whiB2, wloB2, g_h1h[p ^ 1], g_h1l[p ^ 1], lane, wid);
#pragma unroll
        for (int j = 0; j < 2; ++j) {
            float gi = acc[0][0][j*2]   + acc[1][0][j*2]   + acc[2][0][j*2]   + b2g[0];
            float gf = acc[0][0][j*2+1] + acc[1][0][j*2+1] + acc[2][0][j*2+1] + b2g[1];
            float gg = acc[0][1][j*2]   + acc[1][1][j*2]   + acc[2][1][j*2]   + b2g[2];
            float go = acc[0][1][j*2+1] + acc[1][1][j*2+1] + acc[2][1][j*2+1] + b2g[3];
            float ii = 1.f / (1.f + expf(-gi));
            float ff = 1.f / (1.f + expf(-gf));
            float g_ = tanhf(gg);
            float oo = 1.f / (1.f + expf(-go));
            c2[j] = ff * c2[j] + ii * g_;
            float hv = oo * tanhf(c2[j]);
            __nv_bfloat16 bh = __float2bfloat16(hv);
            __nv_bfloat16 bl = __float2bfloat16(hv - __bfloat162float(bh));
            st16g(g_h2h[q ^ 1], fidx + j, hf, bfbits(bh));
            st16g(g_h2l[q ^ 1], fidx + j, hf, bfbits(bl));
            __stcg(g_h2p[q ^ 1] + (j ? b1 : b0) * HID + kk, hv);
        }
        grid_barrier(++barno);            // h2_new visible chip-wide

        // ---- Phase C: projection (CTA bid == batch element bid) -----------
        {
            float2 hv = __ldcg((const float2*)(g_h2p[q ^ 1] + bid * HID + 2 * tid));
            float2 wv = __ldg((const float2*)(Wout + 2 * tid));
            float part = hv.x * wv.x + hv.y * wv.y;
#pragma unroll
            for (int s = 16; s; s >>= 1) part += __shfl_xor_sync(0xffffffffu, part, s);
            if (lane == 0) s_red[wid] = part;
            __syncthreads();
            if (tid == 0) {
                float o = s_red[0] + s_red[1] + s_red[2] + s_red[3]
                        + s_red[4] + s_red[5] + s_red[6] + s_red[7] + bo_out;
                out[bid * TF + t] = o;
                __stcg(g_xfeed + bid, o);
            }
        }
        if (t >= T - 1) grid_barrier(++barno);   // feedback consumes 'out'
        else            __syncthreads();         // s_red reuse
        p ^= 1; q ^= 1;
    }
}

// ---------------------------------------------------------------------------
extern "C" void kernel_launch(void* const* d_in, const int* in_sizes, int n_in,
                              void* d_out, int out_size) {
    const float* x    = (const float*)d_in[0];
    const float* Wih1 = (const float*)d_in[2];
    const float* Whh1 = (const float*)d_in[3];
    const float* bih1 = (const float*)d_in[4];
    const float* bhh1 = (const float*)d_in[5];
    const float* Wih2 = (const float*)d_in[6];
    const float* Whh2 = (const float*)d_in[7];
    const float* bih2 = (const float*)d_in[8];
    const float* bhh2 = (const float*)d_in[9];
    const float* Wout = (const float*)d_in[10];
    const float* bout = (const float*)d_in[11];

    int T  = in_sizes[0] / BAT;       // 512
    int TF = out_size / BAT;          // 576
    int F  = TF - T;                  // 64

    const int smem = 24576 * 4;       // 98304 B: 3 matrices x (hi+lo) frag

    cudaFuncSetAttribute(lstm_main, cudaFuncAttributeMaxDynamicSharedMemorySize, smem);

    reset_kernel<<<512, 256>>>(x, T);
    lstm_main<<<NCTA, NTHR, smem>>>(Wih1, Whh1, bih1, bhh1,
                                    Wih2, Whh2, bih2, bhh2,
                                    Wout, bout, (float*)d_out, T, F);
}

// round 9
// speedup vs baseline: 4.0486x; 1.1037x over previous
#include <cuda_runtime.h>
#include <cuda_bf16.h>
#include <math.h>

// ---------------------------------------------------------------------------
// SineLSTM v7 — persistent mma.sync bf16 m16n8k16, fused A+B1 pass,
// acquire/release grid barrier. 128 CTAs x 256 thr.
// h pre-split bf16 hi/lo in gmem fragment order; weights pre-split in SMEM.
// ---------------------------------------------------------------------------

#define NCTA 128
#define NTHR 256
#define HID  512
#define BAT  128

typedef unsigned int u32;

// fragment buffers: [mtile(8)][k16(32)][lane(32)] x uint4 (regs a0..a3, bf16x2)
__device__ __align__(16) uint4 g_h1h[2][8192];
__device__ __align__(16) uint4 g_h1l[2][8192];
__device__ __align__(16) uint4 g_h2h[2][8192];
__device__ __align__(16) uint4 g_h2l[2][8192];
__device__ __align__(16) float g_h2p[2][BAT * HID];   // plain [b][k] for projection
__device__ float g_xT[512 * BAT];                     // [t][b]
__device__ float g_xfeed[BAT];
__device__ unsigned g_arrive[NCTA];
__device__ unsigned g_sense;

// ---------------- helpers ---------------------------------------------------
__device__ __forceinline__ unsigned short bfbits(__nv_bfloat16 v) {
    return reinterpret_cast<unsigned short&>(v);
}
__device__ __forceinline__ void st16g(void* base, int word, int half, unsigned short v) {
    asm volatile("st.global.cg.u16 [%0], %1;"
                 :: "l"((char*)base + (size_t)word * 4 + half * 2), "h"(v) : "memory");
}
__device__ __forceinline__ void st_rel(unsigned* p, unsigned v) {
    asm volatile("st.release.gpu.u32 [%0], %1;" :: "l"(p), "r"(v) : "memory");
}
__device__ __forceinline__ unsigned ld_acq(unsigned* p) {
    unsigned v;
    asm volatile("ld.acquire.gpu.u32 %0, [%1];" : "=r"(v) : "l"(p) : "memory");
    return v;
}

__device__ __forceinline__ void mma16(float* c, uint4 a, u32 b0, u32 b1) {
    asm("mma.sync.aligned.m16n8k16.row.col.f32.bf16.bf16.f32 "
        "{%0,%1,%2,%3}, {%4,%5,%6,%7}, {%8,%9}, {%0,%1,%2,%3};"
        : "+f"(c[0]), "+f"(c[1]), "+f"(c[2]), "+f"(c[3])
        : "r"(a.x), "r"(a.y), "r"(a.z), "r"(a.w), "r"(b0), "r"(b1));
}

// ---------------- grid barrier (release/acquire, no heavyweight fence) ------
__device__ __forceinline__ void grid_barrier(unsigned barno) {
    __syncthreads();
    if (threadIdx.x == 0) st_rel(&g_arrive[blockIdx.x], barno);
    if (blockIdx.x == 0) {
        unsigned v;
        do {
            v = (threadIdx.x < NCTA) ? ld_acq(&g_arrive[threadIdx.x]) : barno;
        } while (__syncthreads_and(v >= barno) == 0);
        if (threadIdx.x == 0) st_rel(&g_sense, barno);
    } else {
        if (threadIdx.x == 0) { while (ld_acq(&g_sense) < barno) {} }
        __syncthreads();
    }
}

// ---------------- fused GEMM pass: layer-1 A and layer-2 B1 together --------
// a1M/a1C: main + merged-correction accumulators for h1_old x Whh1^T,
// a2M/a2C: same for h2_old x Whh2^T. whi* point at hi smem; lo at +1024 uint4.
__device__ __forceinline__ void mma_fused(float (&a1M)[2][4], float (&a1C)[2][4],
                                          float (&a2M)[2][4], float (&a2C)[2][4],
                                          const uint4* __restrict__ wA,
                                          const uint4* __restrict__ wB,
                                          const uint4* __restrict__ g1h,
                                          const uint4* __restrict__ g1l,
                                          const uint4* __restrict__ g2h,
                                          const uint4* __restrict__ g2l,
                                          int lane, int wid) {
    const uint4* p1h = g1h + wid * 1024 + lane;
    const uint4* p1l = g1l + wid * 1024 + lane;
    const uint4* p2h = g2h + wid * 1024 + lane;
    const uint4* p2l = g2l + wid * 1024 + lane;
    uint4 f1h[4], f1l[4], f2h[4], f2l[4];
#pragma unroll
    for (int i = 0; i < 4; ++i) {
        f1h[i] = __ldcg(p1h + i * 32); f1l[i] = __ldcg(p1l + i * 32);
        f2h[i] = __ldcg(p2h + i * 32); f2l[i] = __ldcg(p2l + i * 32);
    }
#pragma unroll 4
    for (int k = 0; k < 32; ++k) {
        uint4 A1h = f1h[k & 3], A1l = f1l[k & 3];
        uint4 A2h = f2h[k & 3], A2l = f2l[k & 3];
        if (k < 28) {
            f1h[k & 3] = __ldcg(p1h + (k + 4) * 32);
            f1l[k & 3] = __ldcg(p1l + (k + 4) * 32);
            f2h[k & 3] = __ldcg(p2h + (k + 4) * 32);
            f2l[k & 3] = __ldcg(p2l + (k + 4) * 32);
        }
        uint4 B1h = wA[k * 32 + lane], B1l = wA[1024 + k * 32 + lane];
        uint4 B2h = wB[k * 32 + lane], B2l = wB[1024 + k * 32 + lane];
        mma16(a1M[0], A1h, B1h.x, B1h.y);
        mma16(a1C[0], A1l, B1h.x, B1h.y);
        mma16(a1C[0], A1h, B1l.x, B1l.y);
        mma16(a1M[1], A1h, B1h.z, B1h.w);
        mma16(a1C[1], A1l, B1h.z, B1h.w);
        mma16(a1C[1], A1h, B1l.z, B1l.w);
        mma16(a2M[0], A2h, B2h.x, B2h.y);
        mma16(a2C[0], A2l, B2h.x, B2h.y);
        mma16(a2C[0], A2h, B2l.x, B2l.y);
        mma16(a2M[1], A2h, B2h.z, B2h.w);
        mma16(a2C[1], A2l, B2h.z, B2h.w);
        mma16(a2C[1], A2h, B2l.z, B2l.w);
    }
}

// ---------------- single GEMM pass (B2), prefetch depth 8 -------------------
__device__ __forceinline__ void mma_single(float (&aM)[2][4], float (&aC)[2][4],
                                           const uint4* __restrict__ wB,
                                           const uint4* __restrict__ gh,
                                           const uint4* __restrict__ gl,
                                           int lane, int wid) {
    const uint4* ph = gh + wid * 1024 + lane;
    const uint4* pl = gl + wid * 1024 + lane;
    uint4 fh[8], fl[8];
#pragma unroll
    for (int i = 0; i < 8; ++i) { fh[i] = __ldcg(ph + i * 32); fl[i] = __ldcg(pl + i * 32); }
#pragma unroll 8
    for (int k = 0; k < 32; ++k) {
        uint4 Ah = fh[k & 7], Al = fl[k & 7];
        if (k < 24) {
            fh[k & 7] = __ldcg(ph + (k + 8) * 32);
            fl[k & 7] = __ldcg(pl + (k + 8) * 32);
        }
        uint4 Bh = wB[k * 32 + lane], Bl = wB[1024 + k * 32 + lane];
        mma16(aM[0], Ah, Bh.x, Bh.y);
        mma16(aC[0], Al, Bh.x, Bh.y);
        mma16(aC[0], Ah, Bl.x, Bl.y);
        mma16(aM[1], Ah, Bh.z, Bh.w);
        mma16(aC[1], Al, Bh.z, Bh.w);
        mma16(aC[1], Ah, Bl.z, Bl.w);
    }
}

__device__ __forceinline__ void zero4(float (&aM)[2][4], float (&aC)[2][4]) {
#pragma unroll
    for (int n = 0; n < 2; ++n)
#pragma unroll
        for (int i = 0; i < 4; ++i) { aM[n][i] = 0.f; aC[n][i] = 0.f; }
}

// ---------------- reset / transpose ----------------------------------------
__global__ void reset_kernel(const float* __restrict__ x, int T) {
    int idx = blockIdx.x * blockDim.x + threadIdx.x;
    uint4 z4 = make_uint4(0, 0, 0, 0);
    if (idx < 16384) {
        ((uint4*)g_h1h)[idx] = z4; ((uint4*)g_h1l)[idx] = z4;
        ((uint4*)g_h2h)[idx] = z4; ((uint4*)g_h2l)[idx] = z4;
    }
    if (idx < 2 * BAT * HID) ((float*)g_h2p)[idx] = 0.f;
    if (idx < BAT * T) {
        int b = idx / T, t = idx - b * T;
        g_xT[t * BAT + b] = x[idx];
    }
    if (idx < NCTA) g_arrive[idx] = 0;
    if (idx < BAT)  g_xfeed[idx] = 0.f;
    if (idx == 0)   g_sense = 0;
}

// ---------------- main persistent kernel -----------------------------------
__global__ void __launch_bounds__(NTHR, 1)
lstm_main(const float* __restrict__ Wih1, const float* __restrict__ Whh1,
          const float* __restrict__ bih1, const float* __restrict__ bhh1,
          const float* __restrict__ Wih2, const float* __restrict__ Whh2,
          const float* __restrict__ bih2, const float* __restrict__ bhh2,
          const float* __restrict__ Wout, const float* __restrict__ bout,
          float* __restrict__ out, int T, int F) {
    extern __shared__ float sm[];
    __shared__ float s_red[8];

    const int tid  = threadIdx.x;
    const int lane = tid & 31;
    const int wid  = tid >> 5;            // warp = m-tile (16 batches)
    const int bid  = blockIdx.x;
    const int r    = lane >> 2;           // fragment row 0..7
    const int u    = lane & 3;            // this thread's hidden unit (of CTA's 4)

    // ---- one-time: split weights into SMEM bf16 fragment layout -----------
    {
        const float* Ws[3] = { Whh1, Whh2, Wih2 };
        for (int idx = tid; idx < 8192; idx += NTHR) {
            int n = idx >> 9, k = idx & 511;
            int uu = (n & 7) >> 1, g = (n & 1) + 2 * (n >> 3);
            int row = g * HID + bid * 4 + uu;
            int k16 = k >> 4, kc = k & 15;
            int ln  = (n & 7) * 4 + ((kc & 7) >> 1);
            int word = (k16 * 32 + ln) * 4 + (n >> 3) * 2 + (kc >> 3);
            int half = kc & 1;
#pragma unroll
            for (int m = 0; m < 3; ++m) {
                float w = __ldg(Ws[m] + row * HID + k);
                __nv_bfloat16 bh = __float2bfloat16(w);
                __nv_bfloat16 bl = __float2bfloat16(w - __bfloat162float(bh));
                ((unsigned short*)(sm + m * 8192))[word * 2 + half]        = bfbits(bh);
                ((unsigned short*)(sm + m * 8192 + 4096))[word * 2 + half] = bfbits(bl);
            }
        }
    }
    float b1g[4], b2g[4], wxg[4];
#pragma unroll
    for (int g = 0; g < 4; ++g) {
        int row = g * HID + bid * 4 + u;
        b1g[g] = __ldg(bih1 + row) + __ldg(bhh1 + row);
        b2g[g] = __ldg(bih2 + row) + __ldg(bhh2 + row);
        wxg[g] = __ldg(Wih1 + row);
    }
    const float bo_out = __ldg(bout);
    __syncthreads();

    const uint4* wA  = (const uint4*)sm;              // Whh1 hi (lo at +1024)
    const uint4* wB1 = (const uint4*)(sm + 8192);     // Whh2
    const uint4* wB2 = (const uint4*)(sm + 16384);    // Wih2

    const int b0 = wid * 16 + r;
    const int b1 = b0 + 8;
    const int kk = 4 * bid + u;
    const int q16 = bid >> 2;
    const int kc  = 4 * (bid & 3) + u;
    const int Ls  = r * 4 + ((kc & 7) >> 1);
    const int rb  = (kc >= 8) ? 2 : 0;
    const int hf  = kc & 1;
    const int fidx = ((wid * 32 + q16) * 32 + Ls) * 4 + rb;

    const int TF = T + F;
    float c1[2] = {0.f, 0.f}, c2[2] = {0.f, 0.f};
    int p = 0, q = 0;
    unsigned barno = 0;
    float a1M[2][4], a1C[2][4], a2M[2][4], a2C[2][4];

    for (int t = 0; t < TF; ++t) {
        // ---- fused Phase A (h1_old x Whh1^T) + Phase B1 (h2_old x Whh2^T) --
        const float* xsrc = (t < T) ? (g_xT + t * BAT) : g_xfeed;
        float xq[2] = { __ldcg(xsrc + b0), __ldcg(xsrc + b1) };

        zero4(a1M, a1C);
        zero4(a2M, a2C);
        mma_fused(a1M, a1C, a2M, a2C, wA, wB1,
                  g_h1h[p], g_h1l[p], g_h2h[q], g_h2l[q], lane, wid);

        // ---- epilogue layer 1 ---------------------------------------------
#pragma unroll
        for (int j = 0; j < 2; ++j) {
            float gi = a1M[0][j*2]   + a1C[0][j*2]   + b1g[0] + wxg[0] * xq[j];
            float gf = a1M[0][j*2+1] + a1C[0][j*2+1] + b1g[1] + wxg[1] * xq[j];
            float gg = a1M[1][j*2]   + a1C[1][j*2]   + b1g[2] + wxg[2] * xq[j];
            float go = a1M[1][j*2+1] + a1C[1][j*2+1] + b1g[3] + wxg[3] * xq[j];
            float ii = 1.f / (1.f + expf(-gi));
            float ff = 1.f / (1.f + expf(-gf));
            float g_ = tanhf(gg);
            float oo = 1.f / (1.f + expf(-go));
            c1[j] = ff * c1[j] + ii * g_;
            float hv = oo * tanhf(c1[j]);
            __nv_bfloat16 bh = __float2bfloat16(hv);
            __nv_bfloat16 bl = __float2bfloat16(hv - __bfloat162float(bh));
            st16g(g_h1h[p ^ 1], fidx + j, hf, bfbits(bh));
            st16g(g_h1l[p ^ 1], fidx + j, hf, bfbits(bl));
        }
        grid_barrier(++barno);            // h1_new visible chip-wide

        // ---- Phase B2: += h1_new x Wih2^T ---------------------------------
        mma_single(a2M, a2C, wB2, g_h1h[p ^ 1], g_h1l[p ^ 1], lane, wid);
#pragma unroll
        for (int j = 0; j < 2; ++j) {
            float gi = a2M[0][j*2]   + a2C[0][j*2]   + b2g[0];
            float gf = a2M[0][j*2+1] + a2C[0][j*2+1] + b2g[1];
            float gg = a2M[1][j*2]   + a2C[1][j*2]   + b2g[2];
            float go = a2M[1][j*2+1] + a2C[1][j*2+1] + b2g[3];
            float ii = 1.f / (1.f + expf(-gi));
            float ff = 1.f / (1.f + expf(-gf));
            float g_ = tanhf(gg);
            float oo = 1.f / (1.f + expf(-go));
            c2[j] = ff * c2[j] + ii * g_;
            float hv = oo * tanhf(c2[j]);
            __nv_bfloat16 bh = __float2bfloat16(hv);
            __nv_bfloat16 bl = __float2bfloat16(hv - __bfloat162float(bh));
            st16g(g_h2h[q ^ 1], fidx + j, hf, bfbits(bh));
            st16g(g_h2l[q ^ 1], fidx + j, hf, bfbits(bl));
            __stcg(g_h2p[q ^ 1] + (j ? b1 : b0) * HID + kk, hv);
        }
        grid_barrier(++barno);            // h2_new visible chip-wide

        // ---- Phase C: projection (CTA bid == batch element bid) -----------
        {
            float2 hv = __ldcg((const float2*)(g_h2p[q ^ 1] + bid * HID + 2 * tid));
            float2 wv = __ldg((const float2*)(Wout + 2 * tid));
            float part = hv.x * wv.x + hv.y * wv.y;
#pragma unroll
            for (int s = 16; s; s >>= 1) part += __shfl_xor_sync(0xffffffffu, part, s);
            if (lane == 0) s_red[wid] = part;
            __syncthreads();
            if (tid == 0) {
                float o = s_red[0] + s_red[1] + s_red[2] + s_red[3]
                        + s_red[4] + s_red[5] + s_red[6] + s_red[7] + bo_out;
                out[bid * TF + t] = o;
                __stcg(g_xfeed + bid, o);
            }
        }
        if (t >= T - 1) grid_barrier(++barno);   // feedback consumes 'out'
        else            __syncthreads();         // s_red reuse
        p ^= 1; q ^= 1;
    }
}

// ---------------------------------------------------------------------------
extern "C" void kernel_launch(void* const* d_in, const int* in_sizes, int n_in,
                              void* d_out, int out_size) {
    const float* x    = (const float*)d_in[0];
    const float* Wih1 = (const float*)d_in[2];
    const float* Whh1 = (const float*)d_in[3];
    const float* bih1 = (const float*)d_in[4];
    const float* bhh1 = (const float*)d_in[5];
    const float* Wih2 = (const float*)d_in[6];
    const float* Whh2 = (const float*)d_in[7];
    const float* bih2 = (const float*)d_in[8];
    const float* bhh2 = (const float*)d_in[9];
    const float* Wout = (const float*)d_in[10];
    const float* bout = (const float*)d_in[11];

    int T  = in_sizes[0] / BAT;       // 512
    int TF = out_size / BAT;          // 576
    int F  = TF - T;                  // 64

    const int smem = 24576 * 4;       // 98304 B

    cudaFuncSetAttribute(lstm_main, cudaFuncAttributeMaxDynamicSharedMemorySize, smem);

    reset_kernel<<<512, 256>>>(x, T);
    lstm_main<<<NCTA, NTHR, smem>>>(Wih1, Whh1, bih1, bhh1,
                                    Wih2, Whh2, bih2, bhh2,
                                    Wout, bout, (float*)d_out, T, F);
}

// round 10
// speedup vs baseline: 5.1675x; 1.2764x over previous
#include <cuda_runtime.h>
#include <cuda_bf16.h>
#include <math.h>

// ---------------------------------------------------------------------------
// SineLSTM v8 — layer-pipelined persistent bf16 m16n8k16 kernel.
// Superstep s computes h1(s) AND h2(s-1) in ONE fused GEMM pass (3 products),
// one grid barrier per sequence step. 128 CTAs x 256 thr.
// ---------------------------------------------------------------------------

#define NCTA 128
#define NTHR 256
#define HID  512
#define BAT  128

typedef unsigned int u32;

// fragment buffers: [mtile(8)][k16(32)][lane(32)] x uint4 (regs a0..a3, bf16x2)
__device__ __align__(16) uint4 g_h1h[2][8192];
__device__ __align__(16) uint4 g_h1l[2][8192];
__device__ __align__(16) uint4 g_h2h[2][8192];
__device__ __align__(16) uint4 g_h2l[2][8192];
__device__ __align__(16) float g_h2p[2][BAT * HID];   // plain [b][k] for projection
__device__ float g_xT[512 * BAT];                     // [t][b]
__device__ float g_xfeed[BAT];
__device__ unsigned g_arrive[NCTA];
__device__ unsigned g_sense;

// ---------------- helpers ---------------------------------------------------
__device__ __forceinline__ unsigned short bfbits(__nv_bfloat16 v) {
    return reinterpret_cast<unsigned short&>(v);
}
__device__ __forceinline__ void st16g(void* base, int word, int half, unsigned short v) {
    asm volatile("st.global.cg.u16 [%0], %1;"
                 :: "l"((char*)base + (size_t)word * 4 + half * 2), "h"(v) : "memory");
}
__device__ __forceinline__ void st_rel(unsigned* p, unsigned v) {
    asm volatile("st.release.gpu.u32 [%0], %1;" :: "l"(p), "r"(v) : "memory");
}
__device__ __forceinline__ unsigned ld_acq(unsigned* p) {
    unsigned v;
    asm volatile("ld.acquire.gpu.u32 %0, [%1];" : "=r"(v) : "l"(p) : "memory");
    return v;
}

__device__ __forceinline__ void mma16(float* c, uint4 a, u32 b0, u32 b1) {
    asm("mma.sync.aligned.m16n8k16.row.col.f32.bf16.bf16.f32 "
        "{%0,%1,%2,%3}, {%4,%5,%6,%7}, {%8,%9}, {%0,%1,%2,%3};"
        : "+f"(c[0]), "+f"(c[1]), "+f"(c[2]), "+f"(c[3])
        : "r"(a.x), "r"(a.y), "r"(a.z), "r"(a.w), "r"(b0), "r"(b1));
}

// ---------------- grid barrier (release/acquire) ----------------------------
__device__ __forceinline__ void grid_barrier(unsigned barno) {
    __syncthreads();
    if (threadIdx.x == 0) st_rel(&g_arrive[blockIdx.x], barno);
    if (blockIdx.x == 0) {
        unsigned v;
        do {
            v = (threadIdx.x < NCTA) ? ld_acq(&g_arrive[threadIdx.x]) : barno;
        } while (__syncthreads_and(v >= barno) == 0);
        if (threadIdx.x == 0) st_rel(&g_sense, barno);
    } else {
        if (threadIdx.x == 0) { while (ld_acq(&g_sense) < barno) {} }
        __syncthreads();
    }
}

// ---------------- fused triple GEMM pass ------------------------------------
// acc1 += h1 x Whh1^T ; acc2 += h1 x Wih2^T + h2 x Whh2^T. Warp wid = m-tile.
__device__ __forceinline__ void mma_fused3(float (&a1M)[2][4], float (&a1C)[2][4],
                                           float (&a2M)[2][4], float (&a2C)[2][4],
                                           const uint4* __restrict__ wA,
                                           const uint4* __restrict__ wH,
                                           const uint4* __restrict__ wI,
                                           const uint4* __restrict__ g1h,
                                           const uint4* __restrict__ g1l,
                                           const uint4* __restrict__ g2h,
                                           const uint4* __restrict__ g2l,
                                           int lane, int wid) {
    const uint4* p1h = g1h + wid * 1024 + lane;
    const uint4* p1l = g1l + wid * 1024 + lane;
    const uint4* p2h = g2h + wid * 1024 + lane;
    const uint4* p2l = g2l + wid * 1024 + lane;
    uint4 f1h[4], f1l[4], f2h[4], f2l[4];
#pragma unroll
    for (int i = 0; i < 4; ++i) {
        f1h[i] = __ldcg(p1h + i * 32); f1l[i] = __ldcg(p1l + i * 32);
        f2h[i] = __ldcg(p2h + i * 32); f2l[i] = __ldcg(p2l + i * 32);
    }
#pragma unroll 4
    for (int k = 0; k < 32; ++k) {
        uint4 A1h = f1h[k & 3], A1l = f1l[k & 3];
        uint4 A2h = f2h[k & 3], A2l = f2l[k & 3];
        if (k < 28) {
            f1h[k & 3] = __ldcg(p1h + (k + 4) * 32);
            f1l[k & 3] = __ldcg(p1l + (k + 4) * 32);
            f2h[k & 3] = __ldcg(p2h + (k + 4) * 32);
            f2l[k & 3] = __ldcg(p2l + (k + 4) * 32);
        }
        uint4 WAh = wA[k * 32 + lane], WAl = wA[1024 + k * 32 + lane];
        uint4 WHh = wH[k * 32 + lane], WHl = wH[1024 + k * 32 + lane];
        uint4 WIh = wI[k * 32 + lane], WIl = wI[1024 + k * 32 + lane];
        // layer 1: h1 x Whh1
        mma16(a1M[0], A1h, WAh.x, WAh.y);
        mma16(a1C[0], A1l, WAh.x, WAh.y);
        mma16(a1C[0], A1h, WAl.x, WAl.y);
        mma16(a1M[1], A1h, WAh.z, WAh.w);
        mma16(a1C[1], A1l, WAh.z, WAh.w);
        mma16(a1C[1], A1h, WAl.z, WAl.w);
        // layer 2 part 1: h1 x Wih2
        mma16(a2M[0], A1h, WIh.x, WIh.y);
        mma16(a2C[0], A1l, WIh.x, WIh.y);
        mma16(a2C[0], A1h, WIl.x, WIl.y);
        mma16(a2M[1], A1h, WIh.z, WIh.w);
        mma16(a2C[1], A1l, WIh.z, WIh.w);
        mma16(a2C[1], A1h, WIl.z, WIl.w);
        // layer 2 part 2: h2 x Whh2
        mma16(a2M[0], A2h, WHh.x, WHh.y);
        mma16(a2C[0], A2l, WHh.x, WHh.y);
        mma16(a2C[0], A2h, WHl.x, WHl.y);
        mma16(a2M[1], A2h, WHh.z, WHh.w);
        mma16(a2C[1], A2l, WHh.z, WHh.w);
        mma16(a2C[1], A2h, WHl.z, WHl.w);
    }
}

__device__ __forceinline__ void zero4(float (&aM)[2][4], float (&aC)[2][4]) {
#pragma unroll
    for (int n = 0; n < 2; ++n)
#pragma unroll
        for (int i = 0; i < 4; ++i) { aM[n][i] = 0.f; aC[n][i] = 0.f; }
}

// ---------------- reset / transpose ----------------------------------------
__global__ void reset_kernel(const float* __restrict__ x, int T) {
    int idx = blockIdx.x * blockDim.x + threadIdx.x;
    uint4 z4 = make_uint4(0, 0, 0, 0);
    if (idx < 16384) {
        ((uint4*)g_h1h)[idx] = z4; ((uint4*)g_h1l)[idx] = z4;
        ((uint4*)g_h2h)[idx] = z4; ((uint4*)g_h2l)[idx] = z4;
    }
    if (idx < 2 * BAT * HID) ((float*)g_h2p)[idx] = 0.f;
    if (idx < BAT * T) {
        int b = idx / T, t = idx - b * T;
        g_xT[t * BAT + b] = x[idx];
    }
    if (idx < NCTA) g_arrive[idx] = 0;
    if (idx < BAT)  g_xfeed[idx] = 0.f;
    if (idx == 0)   g_sense = 0;
}

// ---------------- main persistent kernel -----------------------------------
__global__ void __launch_bounds__(NTHR, 1)
lstm_main(const float* __restrict__ Wih1, const float* __restrict__ Whh1,
          const float* __restrict__ bih1, const float* __restrict__ bhh1,
          const float* __restrict__ Wih2, const float* __restrict__ Whh2,
          const float* __restrict__ bih2, const float* __restrict__ bhh2,
          const float* __restrict__ Wout, const float* __restrict__ bout,
          float* __restrict__ out, int T, int F) {
    extern __shared__ float sm[];
    __shared__ float s_red[8];

    const int tid  = threadIdx.x;
    const int lane = tid & 31;
    const int wid  = tid >> 5;            // warp = m-tile (16 batches)
    const int bid  = blockIdx.x;
    const int r    = lane >> 2;           // fragment row 0..7
    const int u    = lane & 3;            // this thread's hidden unit (of CTA's 4)

    // ---- one-time: split weights into SMEM bf16 fragment layout -----------
    {
        const float* Ws[3] = { Whh1, Whh2, Wih2 };
        for (int idx = tid; idx < 8192; idx += NTHR) {
            int n = idx >> 9, k = idx & 511;
            int uu = (n & 7) >> 1, g = (n & 1) + 2 * (n >> 3);
            int row = g * HID + bid * 4 + uu;
            int k16 = k >> 4, kc = k & 15;
            int ln  = (n & 7) * 4 + ((kc & 7) >> 1);
            int word = (k16 * 32 + ln) * 4 + (n >> 3) * 2 + (kc >> 3);
            int half = kc & 1;
#pragma unroll
            for (int m = 0; m < 3; ++m) {
                float w = __ldg(Ws[m] + row * HID + k);
                __nv_bfloat16 bh = __float2bfloat16(w);
                __nv_bfloat16 bl = __float2bfloat16(w - __bfloat162float(bh));
                ((unsigned short*)(sm + m * 8192))[word * 2 + half]        = bfbits(bh);
                ((unsigned short*)(sm + m * 8192 + 4096))[word * 2 + half] = bfbits(bl);
            }
        }
    }
    float b1g[4], b2g[4], wxg[4];
#pragma unroll
    for (int g = 0; g < 4; ++g) {
        int row = g * HID + bid * 4 + u;
        b1g[g] = __ldg(bih1 + row) + __ldg(bhh1 + row);
        b2g[g] = __ldg(bih2 + row) + __ldg(bhh2 + row);
        wxg[g] = __ldg(Wih1 + row);
    }
    const float bo_out = __ldg(bout);
    __syncthreads();

    const uint4* wA = (const uint4*)sm;              // Whh1 (lo at +1024)
    const uint4* wH = (const uint4*)(sm + 8192);     // Whh2
    const uint4* wI = (const uint4*)(sm + 16384);    // Wih2

    const int b0 = wid * 16 + r;
    const int b1 = b0 + 8;
    const int kk = 4 * bid + u;
    const int q16 = bid >> 2;
    const int kc  = 4 * (bid & 3) + u;
    const int Ls  = r * 4 + ((kc & 7) >> 1);
    const int rb  = (kc >= 8) ? 2 : 0;
    const int hf  = kc & 1;
    const int fidx = ((wid * 32 + q16) * 32 + Ls) * 4 + rb;

    const int TF = T + F;
    float c1[2] = {0.f, 0.f}, c2[2] = {0.f, 0.f};
    int p = 0, q = 0;
    unsigned barno = 0;
    float a1M[2][4], a1C[2][4], a2M[2][4], a2C[2][4];

    // ---- inline lambdas as macros -----------------------------------------
#define PROJECT(bufq, tpos, feed)                                              \
    do {                                                                       \
        float2 hv = __ldcg((const float2*)(g_h2p[bufq] + bid * HID + 2 * tid));\
        float2 wv = __ldg((const float2*)(Wout + 2 * tid));                    \
        float part = hv.x * wv.x + hv.y * wv.y;                                \
        _Pragma("unroll")                                                      \
        for (int sh = 16; sh; sh >>= 1)                                        \
            part += __shfl_xor_sync(0xffffffffu, part, sh);                    \
        if (lane == 0) s_red[wid] = part;                                      \
        __syncthreads();                                                       \
        if (tid == 0) {                                                        \
            float o = s_red[0] + s_red[1] + s_red[2] + s_red[3]                \
                    + s_red[4] + s_red[5] + s_red[6] + s_red[7] + bo_out;      \
            out[bid * TF + (tpos)] = o;                                        \
            if (feed) __stcg(g_xfeed + bid, o);                                \
        }                                                                      \
        __syncthreads();                                                       \
    } while (0)

#define EPILOGUE1(xq0, xq1)                                                    \
    do {                                                                       \
        float xq[2] = { xq0, xq1 };                                            \
        _Pragma("unroll")                                                      \
        for (int j = 0; j < 2; ++j) {                                          \
            float gi = a1M[0][j*2]   + a1C[0][j*2]   + b1g[0] + wxg[0] * xq[j];\
            float gf = a1M[0][j*2+1] + a1C[0][j*2+1] + b1g[1] + wxg[1] * xq[j];\
            float gg = a1M[1][j*2]   + a1C[1][j*2]   + b1g[2] + wxg[2] * xq[j];\
            float go = a1M[1][j*2+1] + a1C[1][j*2+1] + b1g[3] + wxg[3] * xq[j];\
            float ii = 1.f / (1.f + expf(-gi));                                \
            float ff = 1.f / (1.f + expf(-gf));                                \
            float g_ = tanhf(gg);                                              \
            float oo = 1.f / (1.f + expf(-go));                                \
            c1[j] = ff * c1[j] + ii * g_;                                      \
            float hv = oo * tanhf(c1[j]);                                      \
            __nv_bfloat16 bh = __float2bfloat16(hv);                           \
            __nv_bfloat16 bl = __float2bfloat16(hv - __bfloat162float(bh));    \
            st16g(g_h1h[p ^ 1], fidx + j, hf, bfbits(bh));                     \
            st16g(g_h1l[p ^ 1], fidx + j, hf, bfbits(bl));                     \
        }                                                                      \
    } while (0)

#define EPILOGUE2()                                                            \
    do {                                                                       \
        _Pragma("unroll")                                                      \
        for (int j = 0; j < 2; ++j) {                                          \
            float gi = a2M[0][j*2]   + a2C[0][j*2]   + b2g[0];                 \
            float gf = a2M[0][j*2+1] + a2C[0][j*2+1] + b2g[1];                 \
            float gg = a2M[1][j*2]   + a2C[1][j*2]   + b2g[2];                 \
            float go = a2M[1][j*2+1] + a2C[1][j*2+1] + b2g[3];                 \
            float ii = 1.f / (1.f + expf(-gi));                                \
            float ff = 1.f / (1.f + expf(-gf));                                \
            float g_ = tanhf(gg);                                              \
            float oo = 1.f / (1.f + expf(-go));                                \
            c2[j] = ff * c2[j] + ii * g_;                                      \
            float hv = oo * tanhf(c2[j]);                                      \
            __nv_bfloat16 bh = __float2bfloat16(hv);                           \
            __nv_bfloat16 bl = __float2bfloat16(hv - __bfloat162float(bh));    \
            st16g(g_h2h[q ^ 1], fidx + j, hf, bfbits(bh));                     \
            st16g(g_h2l[q ^ 1], fidx + j, hf, bfbits(bl));                     \
            __stcg(g_h2p[q ^ 1] + (j ? b1 : b0) * HID + kk, hv);               \
        }                                                                      \
    } while (0)

    // ================= sequence supersteps s = 0..T-1 ======================
    // superstep s: computes h1(s) [layer1] and h2(s-1) [layer2]; emits out(s-2)
    for (int s = 0; s < T; ++s) {
        if (s >= 2) PROJECT(q, s - 2, false);

        zero4(a1M, a1C);
        zero4(a2M, a2C);
        mma_fused3(a1M, a1C, a2M, a2C, wA, wH, wI,
                   g_h1h[p], g_h1l[p], g_h2h[q], g_h2l[q], lane, wid);

        {
            const float* xsrc = g_xT + s * BAT;
            EPILOGUE1(__ldcg(xsrc + b0), __ldcg(xsrc + b1));
        }
        if (s > 0) EPILOGUE2();      // h2(s-1); at s=0 stays zero
        grid_barrier(++barno);
        p ^= 1; q ^= 1;
    }

    // ================= feedback supersteps s = T..TF-1 =====================
    for (int s = T; s < TF; ++s) {
        zero4(a1M, a1C);
        zero4(a2M, a2C);
        mma_fused3(a1M, a1C, a2M, a2C, wA, wH, wI,
                   g_h1h[p], g_h1l[p], g_h2h[q], g_h2l[q], lane, wid);

        EPILOGUE2();                 // h2(s-1)
        grid_barrier(++barno);       // h2(s-1) visible
        if (s == T) PROJECT(q, T - 2, false);   // emit straggler out(T-2)
        PROJECT(q ^ 1, s - 1, true); // out(s-1) -> also xfeed = x(s)
        grid_barrier(++barno);       // xfeed visible
        {
            EPILOGUE1(__ldcg(g_xfeed + b0), __ldcg(g_xfeed + b1));
        }
        grid_barrier(++barno);       // h1(s) visible
        p ^= 1; q ^= 1;
    }

    // ================= final superstep: layer 2 only for h2(TF-1) ==========
    zero4(a1M, a1C);
    zero4(a2M, a2C);
    mma_fused3(a1M, a1C, a2M, a2C, wA, wH, wI,
               g_h1h[p], g_h1l[p], g_h2h[q], g_h2l[q], lane, wid);
    EPILOGUE2();                     // h2(TF-1)
    grid_barrier(++barno);
    PROJECT(q ^ 1, TF - 1, false);   // emit out(TF-1)

#undef PROJECT
#undef EPILOGUE1
#undef EPILOGUE2
}

// ---------------------------------------------------------------------------
extern "C" void kernel_launch(void* const* d_in, const int* in_sizes, int n_in,
                              void* d_out, int out_size) {
    const float* x    = (const float*)d_in[0];
    const float* Wih1 = (const float*)d_in[2];
    const float* Whh1 = (const float*)d_in[3];
    const float* bih1 = (const float*)d_in[4];
    const float* bhh1 = (const float*)d_in[5];
    const float* Wih2 = (const float*)d_in[6];
    const float* Whh2 = (const float*)d_in[7];
    const float* bih2 = (const float*)d_in[8];
    const float* bhh2 = (const float*)d_in[9];
    const float* Wout = (const float*)d_in[10];
    const float* bout = (const float*)d_in[11];

    int T  = in_sizes[0] / BAT;       // 512
    int TF = out_size / BAT;          // 576
    int F  = TF - T;                  // 64

    const int smem = 24576 * 4;       // 98304 B

    cudaFuncSetAttribute(lstm_main, cudaFuncAttributeMaxDynamicSharedMemorySize, smem);

    reset_kernel<<<512, 256>>>(x, T);
    lstm_main<<<NCTA, NTHR, smem>>>(Wih1, Whh1, bih1, bhh1,
                                    Wih2, Whh2, bih2, bhh2,
                                    Wout, bout, (float*)d_out, T, F);
}